// round 17
// baseline (speedup 1.0000x reference)
#include <cuda_runtime.h>
#include <cuda_bf16.h>

// Problem constants
#define B 64
#define L 512
#define T 8
#define D 1024
#define C 3
#define N_HOPS 6
#define MVB 256            // matvec blocks per chain step

// ---------------- device scratch ----------------
__device__ float g_P[7][4][D];          // [k][0]=W^k wa2 (p_k), [k][1+m]=W^k Wout[:,m] (u_{m,k})
__device__ float g_c[5][B][L];          // c_k[b,l] = p_k . e_row
__device__ float g_q[3][6][B][L];       // q[m][k][b,l] = u_{m,k} . e_row
__device__ float g_smb[B][L];           // v_loc * (e . wa1)
__device__ float g_vloc[B][L];
__device__ float g_vec[B][D];           // v_aspect (vec_0)

__device__ __forceinline__ float dot4(const float4 a, const float4 b) {
    return a.x * b.x + a.y * b.y + a.z * b.z + a.w * b.w;
}

__device__ __forceinline__ void ffma2(unsigned long long& d, unsigned long long a,
                                      unsigned long long b) {
    asm("fma.rn.f32x2 %0, %1, %2, %0;" : "+l"(d) : "l"(a), "l"(b));
}

union U2F { unsigned long long u; float2 f; };

__device__ __forceinline__ unsigned long long pk2(float lo, float hi) {
    U2F t; t.f.x = lo; t.f.y = hi; return t.u;
}
__device__ __forceinline__ float2 up2(unsigned long long u) {
    U2F t; t.u = u; return t.f;
}
__device__ __forceinline__ unsigned long long add2(unsigned long long a,
                                                   unsigned long long b) {
    U2F x, y; x.u = a; y.u = b;
    x.f.x += y.f.x; x.f.y += y.f.y;
    return x.u;
}

// ---------------- reduction helper (512-thread blocks) ---------------------------
template <int NV>
__device__ __forceinline__ void block_multired(float* v, float* scratch /*16*NV*/,
                                               float* out /*NV*/, int tid) {
    int lane = tid & 31, wid = tid >> 5;
    #pragma unroll
    for (int i = 0; i < NV; i++)
        #pragma unroll
        for (int o = 16; o > 0; o >>= 1)
            v[i] += __shfl_xor_sync(0xffffffffu, v[i], o);
    if (lane == 0)
        #pragma unroll
        for (int i = 0; i < NV; i++) scratch[wid * NV + i] = v[i];
    __syncthreads();
    if (tid < NV) {
        float s = 0.f;
        #pragma unroll
        for (int w = 0; w < 16; w++) s += scratch[w * NV + tid];
        out[tid] = s;
    }
    __syncthreads();
}

// ---------------- matvec step body (4 rows/block, R14-proven) --------------------
__device__ __forceinline__ void matvec_role(const float* __restrict__ W, int k,
                                            int vbid, int tid, float (*scr)[4]) {
    int r = tid >> 6;
    int i = tid & 63;
    int row = vbid * 4 + r;
    const float4* wrow = (const float4*)(W + (long)row * D);

    float4 w0 = wrow[i];
    float4 w1 = wrow[i + 64];
    float4 w2 = wrow[i + 128];
    float4 w3 = wrow[i + 192];

    float acc[4];
    #pragma unroll
    for (int c = 0; c < 4; c++) {
        const float4* p4 = (const float4*)g_P[k][c];
        acc[c] = dot4(w0, p4[i]) + dot4(w1, p4[i + 64])
               + dot4(w2, p4[i + 128]) + dot4(w3, p4[i + 192]);
    }

    #pragma unroll
    for (int c = 0; c < 4; c++)
        #pragma unroll
        for (int o = 16; o > 0; o >>= 1)
            acc[c] += __shfl_xor_sync(0xffffffffu, acc[c], o);

    int lane = tid & 31, warp = tid >> 5;
    if (lane == 0)
        #pragma unroll
        for (int c = 0; c < 4; c++) scr[warp][c] = acc[c];
    __syncthreads();

    if (tid < 16) {
        int rr = tid >> 2, c = tid & 3;
        g_P[k + 1][c][vbid * 4 + rr] = scr[2 * rr][c] + scr[2 * rr + 1][c];
    }
}

// ---------------- kernel: init projection chain (k=0) ----------------------------
__global__ void proj_init_k(const float* __restrict__ wattn,
                            const float* __restrict__ Wout) {
    int d = blockIdx.x * 256 + threadIdx.x;
    g_P[0][0][d] = wattn[D + d];
    #pragma unroll
    for (int m = 0; m < C; m++) g_P[0][1 + m][d] = Wout[d * C + m];
}

// ---------------- kernel: standalone chain step (k=0..3) -------------------------
__global__ void __launch_bounds__(256) matvec4_k(const float* __restrict__ W, int k) {
    __shared__ float scr[8][4];
    matvec_role(W, k, blockIdx.x, threadIdx.x, scr);
}

// ---------------- kernel: FUSED vaspect + chain step k=4 -------------------------
__global__ void __launch_bounds__(256) vaspect_f_k(const int* __restrict__ tgt,
                                                   const int* __restrict__ tlen,
                                                   const float* __restrict__ emb,
                                                   const float* __restrict__ W) {
    __shared__ float scr[8][4];
    int bid = blockIdx.x;
    int t = threadIdx.x;
    if (bid < MVB) {
        matvec_role(W, 4, bid, t, scr);
        return;
    }
    int b = bid - MVB;
    int n = tlen[b];
    float4 acc = make_float4(0.f, 0.f, 0.f, 0.f);
    #pragma unroll
    for (int i = 0; i < T; i++) {
        if (i < n) {
            int id = tgt[b * T + i];
            float4 e = ((const float4*)(emb + (long)id * D))[t];
            acc.x += e.x; acc.y += e.y; acc.z += e.z; acc.w += e.w;
        }
    }
    float inv = 1.0f / (float)n;
    acc.x *= inv; acc.y *= inv; acc.z *= inv; acc.w *= inv;
    ((float4*)g_vec[b])[t] = acc;
}

// ---------------- kernel: FUSED pass A (24 dots via 2 roles) + chain step k=5 ----
// grid MVB + 2*1024 = 2304 blocks, 256 threads.
// bid<MVB: matvec k=5. Else role = 0: {wa1,p0..p4,u0[0..5]}; role = 1: {u1[*],u2[*]}.
// Each role block covers 32 rows (8 warps x 4). 12 vectors staged as 6 f32x2-paired
// vectors in smem (48 KB, lane-consecutive -> conflict-free LDS.64).
#define STAGEPAIR(j, SA, SB)                                        \
    for (int dd = tid; dd < 1024; dd += 256)                        \
        sPP[(j) * 1024 + dd] = pk2((SA)[dd], (SB)[dd]);

__global__ void __launch_bounds__(256) preA_f_k(const int* __restrict__ ctx,
                                                const int* __restrict__ clen,
                                                const int* __restrict__ toff,
                                                const float* __restrict__ emb,
                                                const float* __restrict__ wattn,
                                                const float* __restrict__ W) {
    __shared__ unsigned long long sPP[6 * 1024];   // 48 KB exactly
    int tid = threadIdx.x;
    int bid = blockIdx.x;

    if (bid < MVB) {
        matvec_role(W, 5, bid, tid, (float(*)[4])sPP);
        return;
    }
    int idx = bid - MVB;
    int role = idx >> 10;        // 0 or 1
    idx &= 1023;
    int b = idx & 63;
    int ly = idx >> 6;

    if (role == 0) {
        STAGEPAIR(0, wattn,      g_P[0][0]);
        STAGEPAIR(1, g_P[1][0],  g_P[2][0]);
        STAGEPAIR(2, g_P[3][0],  g_P[4][0]);
        STAGEPAIR(3, g_P[0][1],  g_P[1][1]);
        STAGEPAIR(4, g_P[2][1],  g_P[3][1]);
        STAGEPAIR(5, g_P[4][1],  g_P[5][1]);
    } else {
        STAGEPAIR(0, g_P[0][2],  g_P[1][2]);
        STAGEPAIR(1, g_P[2][2],  g_P[3][2]);
        STAGEPAIR(2, g_P[4][2],  g_P[5][2]);
        STAGEPAIR(3, g_P[0][3],  g_P[1][3]);
        STAGEPAIR(4, g_P[2][3],  g_P[3][3]);
        STAGEPAIR(5, g_P[4][3],  g_P[5][3]);
    }
    __syncthreads();

    int lane = tid & 31, warp = tid >> 5;
    int len = clen[b];
    int tofs = toff[b];
    int lbase = ly * 32 + warp * 4;

    const float* erow[4];
    bool valid[4];
    #pragma unroll
    for (int r = 0; r < 4; r++) {
        int l = lbase + r;
        valid[r] = (l < len);
        erow[r] = emb + (long)ctx[b * L + l] * D;
    }

    unsigned long long acc[6][4] = {};
    #pragma unroll 4
    for (int i = 0; i < 32; i++) {
        int dd = i * 32 + lane;
        float er[4];
        #pragma unroll
        for (int r = 0; r < 4; r++)
            er[r] = valid[r] ? erow[r][dd] : 0.f;
        unsigned long long ed[4];
        #pragma unroll
        for (int r = 0; r < 4; r++) ed[r] = pk2(er[r], er[r]);
        #pragma unroll
        for (int j = 0; j < 6; j++) {
            unsigned long long pp = sPP[j * 1024 + dd];
            #pragma unroll
            for (int r = 0; r < 4; r++) ffma2(acc[j][r], pp, ed[r]);
        }
    }

    // warp-reduce the 24 packed accumulators
    #pragma unroll
    for (int j = 0; j < 6; j++)
        #pragma unroll
        for (int r = 0; r < 4; r++)
            #pragma unroll
            for (int o = 16; o > 0; o >>= 1)
                acc[j][r] = add2(acc[j][r],
                                 __shfl_xor_sync(0xffffffffu, acc[j][r], o));

    if (lane == 0) {
        #pragma unroll
        for (int r = 0; r < 4; r++) {
            int l = lbase + r;
            float2 j0 = up2(acc[0][r]);
            float2 j1 = up2(acc[1][r]);
            float2 j2 = up2(acc[2][r]);
            float2 j3 = up2(acc[3][r]);
            float2 j4 = up2(acc[4][r]);
            float2 j5 = up2(acc[5][r]);
            if (role == 0) {
                float v = valid[r]
                            ? 1.0f - fabsf((float)(l - tofs)) / (float)len
                            : 0.f;
                g_vloc[b][l] = v;
                g_smb[b][l] = v * j0.x;
                g_c[0][b][l] = j0.y;
                g_c[1][b][l] = j1.x;
                g_c[2][b][l] = j1.y;
                g_c[3][b][l] = j2.x;
                g_c[4][b][l] = j2.y;
                g_q[0][0][b][l] = j3.x;
                g_q[0][1][b][l] = j3.y;
                g_q[0][2][b][l] = j4.x;
                g_q[0][3][b][l] = j4.y;
                g_q[0][4][b][l] = j5.x;
                g_q[0][5][b][l] = j5.y;
            } else {
                g_q[1][0][b][l] = j0.x;
                g_q[1][1][b][l] = j0.y;
                g_q[1][2][b][l] = j1.x;
                g_q[1][3][b][l] = j1.y;
                g_q[1][4][b][l] = j2.x;
                g_q[1][5][b][l] = j2.y;
                g_q[2][0][b][l] = j3.x;
                g_q[2][1][b][l] = j3.y;
                g_q[2][2][b][l] = j4.x;
                g_q[2][3][b][l] = j4.y;
                g_q[2][4][b][l] = j5.x;
                g_q[2][5][b][l] = j5.y;
            }
        }
    }
}

// ---------------- kernel: scalar hop recurrence + FUSED logits -------------------
// grid B, 512 threads (thread = one l). logits_m = sum_h sum_l aw_h[l]*q[m][5-h][l]
//   + u_{m,6}.v0 + sum_k u_{m,k}.blin  (+ bout).
__global__ void scalar_k(const int* __restrict__ clen,
                         const float* __restrict__ blin,
                         const float* __restrict__ battn,
                         const float* __restrict__ bout,
                         float* __restrict__ out) {
    int b = blockIdx.x, t = threadIdx.x;
    __shared__ float scr[16 * 12];
    __shared__ float res12[12];
    __shared__ float t_arr[6];
    __shared__ float beta[6];

    int d = t * 2;
    float2 v0 = *(const float2*)&g_vec[b][d];
    float2 bl = *(const float2*)&blin[d];

    {
        float vals[12];
        #pragma unroll
        for (int k = 0; k < 6; k++) {
            float2 p = *(const float2*)&g_P[k][0][d];
            vals[k] = p.x * v0.x + p.y * v0.y;
            vals[6 + k] = p.x * bl.x + p.y * bl.y;
        }
        block_multired<12>(vals, scr, res12, t);
        if (t < 6) { t_arr[t] = res12[t]; beta[t] = res12[6 + t]; }
        __syncthreads();
    }

    int len = clen[b];
    bool valid = t < len;
    float smb_l = g_smb[b][t];
    float vloc_l = g_vloc[b][t];
    float cv[5];
    #pragma unroll
    for (int k = 0; k < 5; k++) cv[k] = g_c[k][b][t];
    float q[3][6];
    #pragma unroll
    for (int m = 0; m < 3; m++)
        #pragma unroll
        for (int kk = 0; kk < 6; kk++)
            q[m][kk] = g_q[m][kk][b][t];
    float bat = battn[0];

    float lg0 = 0.f, lg1 = 0.f, lg2 = 0.f;

    #pragma unroll
    for (int h = 0; h < N_HOPS; h++) {
        float s = t_arr[0];
        float e = valid ? expf(tanhf(smb_l + s + bat)) : 0.f;   // tanh in [-1,1]
        float ev = e * vloc_l;

        float vals[6];
        vals[0] = e;
        #pragma unroll
        for (int k = 0; k < 5; k++) vals[1 + k] = ev * cv[k];
        block_multired<6>(vals, scr, res12, t);

        float inv_se = 1.0f / res12[0];
        float aw = ev * inv_se;
        lg0 += aw * q[0][5 - h];
        lg1 += aw * q[1][5 - h];
        lg2 += aw * q[2][5 - h];

        if (t == 0) {
            #pragma unroll
            for (int k = 0; k < 5; k++)       // ascending: reads t_arr[k+1] pre-update
                t_arr[k] = res12[1 + k] * inv_se + t_arr[k + 1] + beta[k];
        }
        __syncthreads();
    }

    // per-thread d-slice extras + final reduce
    float pm[3] = {lg0, lg1, lg2};
    #pragma unroll
    for (int m = 0; m < C; m++) {
        float2 u6 = *(const float2*)&g_P[6][1 + m][d];
        float ex = u6.x * v0.x + u6.y * v0.y;
        #pragma unroll
        for (int k = 0; k < 6; k++) {
            float2 uk = *(const float2*)&g_P[k][1 + m][d];
            ex += uk.x * bl.x + uk.y * bl.y;
        }
        pm[m] += ex;
    }
    block_multired<3>(pm, scr, res12, t);
    if (t < C) out[b * C + t] = res12[t] + bout[t];
}

// ---------------- launcher -------------------------------------------------------
extern "C" void kernel_launch(void* const* d_in, const int* in_sizes, int n_in,
                              void* d_out, int out_size) {
    const int*   ctx   = (const int*)d_in[0];
    const int*   tgt   = (const int*)d_in[1];
    const int*   clen  = (const int*)d_in[2];
    const int*   tlen  = (const int*)d_in[3];
    const int*   toff  = (const int*)d_in[4];
    const float* emb   = (const float*)d_in[5];
    const float* Wlin  = (const float*)d_in[6];
    const float* blin  = (const float*)d_in[7];
    const float* wattn = (const float*)d_in[8];
    const float* battn = (const float*)d_in[9];
    const float* Wout  = (const float*)d_in[10];
    const float* bout  = (const float*)d_in[11];
    float* out = (float*)d_out;

    proj_init_k<<<4, 256>>>(wattn, Wout);
    for (int k = 0; k < 4; k++)
        matvec4_k<<<MVB, 256>>>(Wlin, k);
    vaspect_f_k<<<MVB + B, 256>>>(tgt, tlen, emb, Wlin);             // + chain k=4
    preA_f_k<<<MVB + 2048, 256>>>(ctx, clen, toff, emb, wattn, Wlin); // + chain k=5
    scalar_k<<<B, 512>>>(clen, blin, battn, bout, out);
}